// round 1
// baseline (speedup 1.0000x reference)
#include <cuda_runtime.h>
#include <cuda_bf16.h>
#include <math.h>

// ----------------------------------------------------------------------------
// Problem constants
// ----------------------------------------------------------------------------
#define Bn   4
#define Sn   2048
#define Dn   1024
#define Hn   16
#define HDn  64
#define Mrows (Bn*Sn)          // 8192
#define D4   (4*Dn)            // 4096

// ----------------------------------------------------------------------------
// Scratch (device globals -- no allocations allowed)
// ----------------------------------------------------------------------------
__device__ float g_hnorm[(size_t)Mrows * Dn];        //  33.5 MB
__device__ float g_qkv  [(size_t)Mrows * 3 * Dn];    // 100.7 MB
__device__ float g_attn [(size_t)Mrows * Dn];        //  33.5 MB
__device__ float g_h1   [(size_t)Mrows * D4];        // 134.2 MB
__device__ float g_wp   [(size_t)Dn * 3 * Dn];       //  12.6 MB
__device__ float g_bp   [3 * Dn];

// ----------------------------------------------------------------------------
// Pack Wq/Wk/Wv [H,D,HD] -> Wp[D, 3*D] with col = w*1024 + h*64 + k
// ----------------------------------------------------------------------------
__global__ void pack_w_kernel(const float* __restrict__ Wq,
                              const float* __restrict__ Wk,
                              const float* __restrict__ Wv,
                              const float* __restrict__ bq,
                              const float* __restrict__ bk,
                              const float* __restrict__ bv,
                              float* __restrict__ Wp,
                              float* __restrict__ bp)
{
    int idx = blockIdx.x * 256 + threadIdx.x;
    const int per = Dn * Hn * HDn;           // 1048576
    if (idx < 3 * per) {
        int w   = idx / per;
        int rem = idx - w * per;
        int d   = rem >> 10;                 // / 1024
        int c   = rem & 1023;                // h*64 + k
        int h   = c >> 6;
        int k   = c & 63;
        const float* W = (w == 0) ? Wq : (w == 1) ? Wk : Wv;
        Wp[(size_t)d * (3 * Dn) + w * Dn + c] =
            W[(size_t)h * (Dn * HDn) + (size_t)d * HDn + k];
    }
    if (idx < 3 * Dn) {
        int w = idx >> 10;
        int c = idx & 1023;
        bp[idx] = (w == 0 ? bq : w == 1 ? bk : bv)[c];
    }
}

// ----------------------------------------------------------------------------
// LayerNorm: one block per row of 1024, 256 threads (4 elems each)
// ----------------------------------------------------------------------------
__global__ void __launch_bounds__(256) ln_kernel(const float* __restrict__ X,
                                                 const float* __restrict__ gamma,
                                                 const float* __restrict__ beta,
                                                 float* __restrict__ Y)
{
    int row = blockIdx.x;
    int tid = threadIdx.x;
    const float4* xr = (const float4*)(X + (size_t)row * Dn);
    float4 xv = xr[tid];

    __shared__ float red[8];

    float s = xv.x + xv.y + xv.z + xv.w;
    #pragma unroll
    for (int o = 16; o > 0; o >>= 1) s += __shfl_xor_sync(0xffffffffu, s, o);
    if ((tid & 31) == 0) red[tid >> 5] = s;
    __syncthreads();
    float tot = red[0] + red[1] + red[2] + red[3] + red[4] + red[5] + red[6] + red[7];
    float mu = tot * (1.0f / Dn);
    __syncthreads();

    float dx = xv.x - mu, dy = xv.y - mu, dz = xv.z - mu, dw = xv.w - mu;
    float sq = dx * dx + dy * dy + dz * dz + dw * dw;
    #pragma unroll
    for (int o = 16; o > 0; o >>= 1) sq += __shfl_xor_sync(0xffffffffu, sq, o);
    if ((tid & 31) == 0) red[tid >> 5] = sq;
    __syncthreads();
    float var = (red[0] + red[1] + red[2] + red[3] + red[4] + red[5] + red[6] + red[7]) * (1.0f / Dn);
    float inv = rsqrtf(var + 1e-5f);

    float4 gv = ((const float4*)gamma)[tid];
    float4 bv = ((const float4*)beta)[tid];
    float4 out;
    out.x = dx * inv * gv.x + bv.x;
    out.y = dy * inv * gv.y + bv.y;
    out.z = dz * inv * gv.z + bv.z;
    out.w = dw * inv * gv.w + bv.w;
    ((float4*)(Y + (size_t)row * Dn))[tid] = out;
}

// ----------------------------------------------------------------------------
// SGEMM 128x128x8, 256 threads, 8x8 microtile.
// C[M,N] = A[M,K] @ B[K,N] (+bias) (gelu?) (+residual?)
// All dims assumed divisible (M%128==0, N%128==0, K%8==0).
// ----------------------------------------------------------------------------
__device__ __forceinline__ float gelu_exact(float v)
{
    return 0.5f * v * (1.0f + erff(v * 0.70710678118654752f));
}

template <bool GELU, bool RES>
__global__ void __launch_bounds__(256) sgemm_kernel(const float* __restrict__ A,
                                                    const float* __restrict__ B,
                                                    float* __restrict__ C,
                                                    const float* __restrict__ bias,
                                                    const float* __restrict__ residual,
                                                    int M, int N, int K)
{
    __shared__ float As[8][128];
    __shared__ float Bs[8][128];

    int tid = threadIdx.x;
    int bx = blockIdx.x, by = blockIdx.y;
    int tx = tid & 15;          // 0..15 -> N microtile
    int ty = tid >> 4;          // 0..15 -> M microtile

    int a_row = tid >> 1;           // 0..127
    int a_col = (tid & 1) << 2;     // 0 or 4
    int b_row = tid >> 5;           // 0..7
    int b_col = (tid & 31) << 2;    // 0..124

    const float* Ag = A + (size_t)(by * 128 + a_row) * K + a_col;
    const float* Bg = B + (size_t)b_row * N + bx * 128 + b_col;

    float acc[8][8];
    #pragma unroll
    for (int i = 0; i < 8; i++)
        #pragma unroll
        for (int j = 0; j < 8; j++) acc[i][j] = 0.0f;

    for (int k0 = 0; k0 < K; k0 += 8) {
        float4 av = *(const float4*)(Ag + k0);
        float4 bv = *(const float4*)(Bg + (size_t)k0 * N);
        __syncthreads();
        As[a_col + 0][a_row] = av.x;
        As[a_col + 1][a_row] = av.y;
        As[a_col + 2][a_row] = av.z;
        As[a_col + 3][a_row] = av.w;
        *(float4*)&Bs[b_row][b_col] = bv;
        __syncthreads();

        #pragma unroll
        for (int kk = 0; kk < 8; kk++) {
            float a[8], b[8];
            *(float4*)&a[0] = *(const float4*)&As[kk][ty * 8];
            *(float4*)&a[4] = *(const float4*)&As[kk][ty * 8 + 4];
            *(float4*)&b[0] = *(const float4*)&Bs[kk][tx * 8];
            *(float4*)&b[4] = *(const float4*)&Bs[kk][tx * 8 + 4];
            #pragma unroll
            for (int i = 0; i < 8; i++)
                #pragma unroll
                for (int j = 0; j < 8; j++)
                    acc[i][j] = fmaf(a[i], b[j], acc[i][j]);
        }
    }

    #pragma unroll
    for (int i = 0; i < 8; i++) {
        int m = by * 128 + ty * 8 + i;
        #pragma unroll
        for (int j = 0; j < 8; j++) {
            int n = bx * 128 + tx * 8 + j;
            float c = acc[i][j] + bias[n];
            if (GELU) c = gelu_exact(c);
            if (RES)  c += residual[(size_t)m * N + n];
            C[(size_t)m * N + n] = c;
        }
    }
}

// ----------------------------------------------------------------------------
// Flash-style causal attention, fp32.
// QKV: [B*S, 3072] with Q at col h*64, K at 1024+h*64, V at 2048+h*64.
// Out: [B*S, 1024] at col h*64.
// grid = (S/64, B*H), block = 256. Thread (r = tid/4, q = tid&3):
//   score keys t = q*16+j, output cols c = q*16+j.
// ----------------------------------------------------------------------------
#define APITCH 68   // row pitch in floats: 16B aligned AND conflict-free (4*r mod 32)

__global__ void __launch_bounds__(256) attn_kernel(const float* __restrict__ QKV,
                                                   float* __restrict__ Out)
{
    extern __shared__ float sm[];
    float* Qs = sm;
    float* Ks = sm + 64 * APITCH;
    float* Vs = sm + 2 * 64 * APITCH;
    float* Ps = sm + 3 * 64 * APITCH;

    int qb = blockIdx.x;
    int bh = blockIdx.y;
    int b = bh >> 4, h = bh & 15;
    int tid = threadIdx.x;
    int r = tid >> 2;       // 0..63 query row within tile
    int q = tid & 3;        // quad

    const size_t base = (size_t)b * Sn * 3072 + (size_t)h * 64;

    // Load Q tile (pre-scaled by 1/sqrt(HD) = 0.125)
    for (int i = tid; i < 64 * 16; i += 256) {
        int rr = i >> 4, c4 = (i & 15) << 2;
        float4 v = *(const float4*)(QKV + base + (size_t)(qb * 64 + rr) * 3072 + c4);
        float* dst = &Qs[rr * APITCH + c4];
        dst[0] = v.x * 0.125f; dst[1] = v.y * 0.125f;
        dst[2] = v.z * 0.125f; dst[3] = v.w * 0.125f;
    }

    float o[16];
    #pragma unroll
    for (int j = 0; j < 16; j++) o[j] = 0.0f;
    float m_prev = -1e30f, l_prev = 0.0f;
    const int qg = qb * 64 + r;

    for (int kb = 0; kb <= qb; kb++) {
        __syncthreads();
        // Load K and V tiles
        for (int i = tid; i < 64 * 16; i += 256) {
            int rr = i >> 4, c4 = (i & 15) << 2;
            size_t off = base + (size_t)(kb * 64 + rr) * 3072 + c4;
            float4 kv = *(const float4*)(QKV + off + 1024);
            float4 vv = *(const float4*)(QKV + off + 2048);
            *(float4*)&Ks[rr * APITCH + c4] = kv;
            *(float4*)&Vs[rr * APITCH + c4] = vv;
        }
        __syncthreads();

        // Scores: s[j] = Q[r,:] . K[q*16+j,:]
        float s[16];
        #pragma unroll
        for (int j = 0; j < 16; j++) s[j] = 0.0f;
        #pragma unroll 4
        for (int k4 = 0; k4 < 16; k4++) {
            float4 qv = *(const float4*)&Qs[r * APITCH + (k4 << 2)];
            #pragma unroll
            for (int j = 0; j < 16; j++) {
                float4 kv = *(const float4*)&Ks[(q * 16 + j) * APITCH + (k4 << 2)];
                s[j] += qv.x * kv.x + qv.y * kv.y + qv.z * kv.z + qv.w * kv.w;
            }
        }

        // Causal mask + tile max
        float mloc = -1e30f;
        #pragma unroll
        for (int j = 0; j < 16; j++) {
            int tg = kb * 64 + q * 16 + j;
            if (tg > qg) s[j] = -1e30f;
            mloc = fmaxf(mloc, s[j]);
        }
        mloc = fmaxf(mloc, __shfl_xor_sync(0xffffffffu, mloc, 1));
        mloc = fmaxf(mloc, __shfl_xor_sync(0xffffffffu, mloc, 2));

        float m_new = fmaxf(m_prev, mloc);
        float alpha = __expf(m_prev - m_new);

        float lsum = 0.0f;
        #pragma unroll
        for (int j = 0; j < 16; j++) {
            float p = __expf(s[j] - m_new);
            Ps[r * APITCH + q * 16 + j] = p;
            lsum += p;
        }
        lsum += __shfl_xor_sync(0xffffffffu, lsum, 1);
        lsum += __shfl_xor_sync(0xffffffffu, lsum, 2);

        l_prev = l_prev * alpha + lsum;
        m_prev = m_new;
        #pragma unroll
        for (int j = 0; j < 16; j++) o[j] *= alpha;

        __syncwarp();   // P row visibility within the quad (same warp)

        // O[c=q*16+j] += sum_t P[r,t] * V[t,c]
        #pragma unroll 4
        for (int t = 0; t < 64; t++) {
            float pv = Ps[r * APITCH + t];
            const float* vrow = &Vs[t * APITCH + q * 16];
            float4 v0 = *(const float4*)(vrow + 0);
            float4 v1 = *(const float4*)(vrow + 4);
            float4 v2 = *(const float4*)(vrow + 8);
            float4 v3 = *(const float4*)(vrow + 12);
            o[0]  += pv * v0.x; o[1]  += pv * v0.y; o[2]  += pv * v0.z; o[3]  += pv * v0.w;
            o[4]  += pv * v1.x; o[5]  += pv * v1.y; o[6]  += pv * v1.z; o[7]  += pv * v1.w;
            o[8]  += pv * v2.x; o[9]  += pv * v2.y; o[10] += pv * v2.z; o[11] += pv * v2.w;
            o[12] += pv * v3.x; o[13] += pv * v3.y; o[14] += pv * v3.z; o[15] += pv * v3.w;
        }
    }

    float linv = 1.0f / l_prev;
    #pragma unroll
    for (int j = 0; j < 16; j++) o[j] *= linv;

    float* op = Out + (size_t)(b * Sn + qb * 64 + r) * Dn + h * 64 + q * 16;
    *(float4*)(op + 0)  = make_float4(o[0],  o[1],  o[2],  o[3]);
    *(float4*)(op + 4)  = make_float4(o[4],  o[5],  o[6],  o[7]);
    *(float4*)(op + 8)  = make_float4(o[8],  o[9],  o[10], o[11]);
    *(float4*)(op + 12) = make_float4(o[12], o[13], o[14], o[15]);
}

// ----------------------------------------------------------------------------
// Launch
// ----------------------------------------------------------------------------
extern "C" void kernel_launch(void* const* d_in, const int* in_sizes, int n_in,
                              void* d_out, int out_size)
{
    const float* x     = (const float*)d_in[0];
    const float* Wq    = (const float*)d_in[1];
    const float* Wk    = (const float*)d_in[2];
    const float* Wv    = (const float*)d_in[3];
    const float* bq    = (const float*)d_in[4];
    const float* bk    = (const float*)d_in[5];
    const float* bv    = (const float*)d_in[6];
    const float* Wo    = (const float*)d_in[7];
    const float* bo    = (const float*)d_in[8];
    const float* W1    = (const float*)d_in[9];
    const float* b1    = (const float*)d_in[10];
    const float* W2    = (const float*)d_in[11];
    const float* b2    = (const float*)d_in[12];
    const float* gamma = (const float*)d_in[13];
    const float* beta  = (const float*)d_in[14];
    float* out = (float*)d_out;

    float *hnorm, *qkv, *attn, *h1, *wp, *bp;
    cudaGetSymbolAddress((void**)&hnorm, g_hnorm);
    cudaGetSymbolAddress((void**)&qkv,   g_qkv);
    cudaGetSymbolAddress((void**)&attn,  g_attn);
    cudaGetSymbolAddress((void**)&h1,    g_h1);
    cudaGetSymbolAddress((void**)&wp,    g_wp);
    cudaGetSymbolAddress((void**)&bp,    g_bp);

    // 1. pack QKV weights/biases
    pack_w_kernel<<<(3 * Dn * Dn + 255) / 256, 256>>>(Wq, Wk, Wv, bq, bk, bv, wp, bp);

    // 2. LN1
    ln_kernel<<<Mrows, 256>>>(x, gamma, beta, hnorm);

    // 3. QKV GEMM: [8192,1024] @ [1024,3072]
    sgemm_kernel<false, false><<<dim3(3 * Dn / 128, Mrows / 128), 256>>>(
        hnorm, wp, qkv, bp, nullptr, Mrows, 3 * Dn, Dn);

    // 4. attention
    const int attn_smem = 4 * 64 * APITCH * (int)sizeof(float);   // 69632 B
    cudaFuncSetAttribute(attn_kernel, cudaFuncAttributeMaxDynamicSharedMemorySize, attn_smem);
    attn_kernel<<<dim3(Sn / 64, Bn * Hn), 256, attn_smem>>>(qkv, attn);

    // 5. Wo GEMM + residual x -> out
    sgemm_kernel<false, true><<<dim3(Dn / 128, Mrows / 128), 256>>>(
        attn, Wo, out, bo, x, Mrows, Dn, Dn);

    // 6. LN2
    ln_kernel<<<Mrows, 256>>>(out, gamma, beta, hnorm);

    // 7. MLP1 + GELU: [8192,1024] @ [1024,4096]
    sgemm_kernel<true, false><<<dim3(D4 / 128, Mrows / 128), 256>>>(
        hnorm, W1, h1, b1, nullptr, Mrows, D4, Dn);

    // 8. MLP2 + residual out (in-place): [8192,4096] @ [4096,1024]
    sgemm_kernel<false, true><<<dim3(Dn / 128, Mrows / 128), 256>>>(
        h1, W2, out, b2, out, Mrows, Dn, D4);
}

// round 3
// speedup vs baseline: 1.2456x; 1.2456x over previous
#include <cuda_runtime.h>
#include <cuda_bf16.h>
#include <mma.h>
#include <cstdint>
#include <math.h>

using namespace nvcuda;

// ----------------------------------------------------------------------------
// Problem constants
// ----------------------------------------------------------------------------
#define Bn   4
#define Sn   2048
#define Dn   1024
#define Hn   16
#define HDn  64
#define Mrows (Bn*Sn)          // 8192
#define D4   (4*Dn)            // 4096

// ----------------------------------------------------------------------------
// Scratch (device globals -- no allocations allowed)
// ----------------------------------------------------------------------------
__device__ float         g_qkv  [(size_t)Mrows * 3 * Dn];    // fp32 for attention
__device__ __nv_bfloat16 g_hA_hi[(size_t)Mrows * Dn];
__device__ __nv_bfloat16 g_hA_lo[(size_t)Mrows * Dn];
__device__ __nv_bfloat16 g_at_hi[(size_t)Mrows * Dn];
__device__ __nv_bfloat16 g_at_lo[(size_t)Mrows * Dn];
__device__ __nv_bfloat16 g_h1_hi[(size_t)Mrows * D4];
__device__ __nv_bfloat16 g_h1_lo[(size_t)Mrows * D4];
__device__ __nv_bfloat16 g_wqkvT_hi[(size_t)3 * Dn * Dn];    // [3072,1024]
__device__ __nv_bfloat16 g_wqkvT_lo[(size_t)3 * Dn * Dn];
__device__ __nv_bfloat16 g_woT_hi[(size_t)Dn * Dn];          // [1024,1024]
__device__ __nv_bfloat16 g_woT_lo[(size_t)Dn * Dn];
__device__ __nv_bfloat16 g_w1T_hi[(size_t)D4 * Dn];          // [4096,1024]
__device__ __nv_bfloat16 g_w1T_lo[(size_t)D4 * Dn];
__device__ __nv_bfloat16 g_w2T_hi[(size_t)Dn * D4];          // [1024,4096]
__device__ __nv_bfloat16 g_w2T_lo[(size_t)Dn * D4];
__device__ float         g_bp[3 * Dn];

__device__ __forceinline__ void split_bf16(float v, __nv_bfloat16& h, __nv_bfloat16& l) {
    h = __float2bfloat16(v);
    l = __float2bfloat16(v - __bfloat162float(h));
}

// ----------------------------------------------------------------------------
// Transpose + bf16 split: src [Ks, Ns] fp32  ->  dst [Ns, Ks] hi/lo bf16 rows.
// ----------------------------------------------------------------------------
__global__ void transpose_pack_kernel(const float* __restrict__ src,
                                      __nv_bfloat16* __restrict__ dhi,
                                      __nv_bfloat16* __restrict__ dlo,
                                      int Ks, int Ns, long long src_zoff,
                                      int out_row_base, int out_stride)
{
    __shared__ float t[32][33];
    int z = blockIdx.z;
    src += (size_t)z * src_zoff;
    int n0 = blockIdx.x * 32, k0 = blockIdx.y * 32;
    int tx = threadIdx.x, ty = threadIdx.y;
    #pragma unroll
    for (int j = 0; j < 4; j++) {
        int k = k0 + ty + j * 8;
        t[ty + j * 8][tx] = src[(size_t)k * Ns + n0 + tx];
    }
    __syncthreads();
    #pragma unroll
    for (int j = 0; j < 4; j++) {
        int n = n0 + ty + j * 8;
        float v = t[tx][ty + j * 8];
        __nv_bfloat16 h, l; split_bf16(v, h, l);
        size_t o = (size_t)(out_row_base + z * Ns + n) * out_stride + k0 + tx;
        dhi[o] = h; dlo[o] = l;
    }
}

__global__ void bias_pack_kernel(const float* __restrict__ bq,
                                 const float* __restrict__ bk,
                                 const float* __restrict__ bv,
                                 float* __restrict__ bp)
{
    int idx = blockIdx.x * 256 + threadIdx.x;
    if (idx < 3 * Dn) {
        int w = idx >> 10, c = idx & 1023;
        bp[idx] = (w == 0 ? bq : w == 1 ? bk : bv)[c];
    }
}

// ----------------------------------------------------------------------------
// LayerNorm -> bf16 hi/lo. One block per row, 256 threads, 4 elems each.
// ----------------------------------------------------------------------------
__global__ void __launch_bounds__(256) ln_kernel(const float* __restrict__ X,
                                                 const float* __restrict__ gamma,
                                                 const float* __restrict__ beta,
                                                 __nv_bfloat16* __restrict__ Yhi,
                                                 __nv_bfloat16* __restrict__ Ylo)
{
    int row = blockIdx.x;
    int tid = threadIdx.x;
    float4 xv = ((const float4*)(X + (size_t)row * Dn))[tid];

    __shared__ float red[8];
    float s = xv.x + xv.y + xv.z + xv.w;
    #pragma unroll
    for (int o = 16; o > 0; o >>= 1) s += __shfl_xor_sync(0xffffffffu, s, o);
    if ((tid & 31) == 0) red[tid >> 5] = s;
    __syncthreads();
    float mu = (red[0]+red[1]+red[2]+red[3]+red[4]+red[5]+red[6]+red[7]) * (1.0f / Dn);
    __syncthreads();

    float dx = xv.x - mu, dy = xv.y - mu, dz = xv.z - mu, dw = xv.w - mu;
    float sq = dx*dx + dy*dy + dz*dz + dw*dw;
    #pragma unroll
    for (int o = 16; o > 0; o >>= 1) sq += __shfl_xor_sync(0xffffffffu, sq, o);
    if ((tid & 31) == 0) red[tid >> 5] = sq;
    __syncthreads();
    float var = (red[0]+red[1]+red[2]+red[3]+red[4]+red[5]+red[6]+red[7]) * (1.0f / Dn);
    float inv = rsqrtf(var + 1e-5f);

    float4 gv = ((const float4*)gamma)[tid];
    float4 bv = ((const float4*)beta)[tid];
    float o0 = dx*inv*gv.x + bv.x, o1 = dy*inv*gv.y + bv.y;
    float o2 = dz*inv*gv.z + bv.z, o3 = dw*inv*gv.w + bv.w;

    __nv_bfloat16 h[4], l[4];
    split_bf16(o0, h[0], l[0]); split_bf16(o1, h[1], l[1]);
    split_bf16(o2, h[2], l[2]); split_bf16(o3, h[3], l[3]);
    size_t off = (size_t)row * Dn + tid * 4;
    *(__nv_bfloat162*)&Yhi[off]     = __nv_bfloat162(h[0], h[1]);
    *(__nv_bfloat162*)&Yhi[off + 2] = __nv_bfloat162(h[2], h[3]);
    *(__nv_bfloat162*)&Ylo[off]     = __nv_bfloat162(l[0], l[1]);
    *(__nv_bfloat162*)&Ylo[off + 2] = __nv_bfloat162(l[2], l[3]);
}

// ----------------------------------------------------------------------------
// WMMA bf16 GEMM (legacy HMMA path -- tcgen05 unavailable via compute_103 PTX).
// C[128x128 fp32] = A[128,K] . B^T  (B stored as rows = output cols, cols = K)
// hi/lo 3-pass: C = Ah.Bh + Ah.Bl + Al.Bh.
// Block tile 128x128, BK=64, 8 warps (warp tile 64x32), 256 threads.
// ----------------------------------------------------------------------------
__device__ __forceinline__ float gelu_exact(float v) {
    return 0.5f * v * (1.0f + erff(v * 0.70710678118654752f));
}

#define BK     64
#define KPITCH 72            // bf16 elems per smem row (64 + 8 pad; 144B, 16B-mult)
#define TILEB  (128 * KPITCH * 2)   // 18432 B per tile
#define SPITCH 132           // fp32 staging pitch

template <bool GELU_, bool RES_, bool OUTF, bool OUTB>
__global__ void __launch_bounds__(256) mma_gemm_kernel(
    const __nv_bfloat16* __restrict__ Ahi, const __nv_bfloat16* __restrict__ Alo,
    const __nv_bfloat16* __restrict__ Bhi, const __nv_bfloat16* __restrict__ Blo,
    const float* __restrict__ bias, const float* __restrict__ residual,
    float* __restrict__ Cf, __nv_bfloat16* __restrict__ Chi, __nv_bfloat16* __restrict__ Clo,
    int N, int K)
{
    extern __shared__ __align__(128) char smem[];
    __nv_bfloat16* Ah_s = (__nv_bfloat16*)(smem + 0 * TILEB);
    __nv_bfloat16* Al_s = (__nv_bfloat16*)(smem + 1 * TILEB);
    __nv_bfloat16* Bh_s = (__nv_bfloat16*)(smem + 2 * TILEB);
    __nv_bfloat16* Bl_s = (__nv_bfloat16*)(smem + 3 * TILEB);
    float* stg = (float*)smem;   // epilogue staging overlays tiles

    const int tid = threadIdx.x;
    const int wid = tid >> 5;
    const int wm = wid >> 2;          // 0..1  (64-row band)
    const int wn = wid & 3;           // 0..3  (32-col band)
    const int bx = blockIdx.x, by = blockIdx.y;

    const size_t arow = (size_t)by * 128;
    const size_t brow = (size_t)bx * 128;

    wmma::fragment<wmma::accumulator, 16, 16, 16, float> acc[4][2];
    #pragma unroll
    for (int i = 0; i < 4; i++)
        #pragma unroll
        for (int j = 0; j < 2; j++) wmma::fill_fragment(acc[i][j], 0.0f);

    const int nk = K / BK;
    for (int kc = 0; kc < nk; kc++) {
        __syncthreads();
        // Load 4 tiles of 128x64 bf16 (each row = 8 float4). 1024 f4/tile.
        #pragma unroll
        for (int i = 0; i < 4; i++) {
            int idx = tid + i * 256;
            int row = idx >> 3, c = idx & 7;           // c: f4 within row
            size_t ao = (arow + row) * (size_t)K + kc * BK + c * 8;
            size_t bo = (brow + row) * (size_t)K + kc * BK + c * 8;
            int so = row * KPITCH + c * 8;
            *(float4*)&Ah_s[so] = *(const float4*)(Ahi + ao);
            *(float4*)&Al_s[so] = *(const float4*)(Alo + ao);
            *(float4*)&Bh_s[so] = *(const float4*)(Bhi + bo);
            *(float4*)&Bl_s[so] = *(const float4*)(Blo + bo);
        }
        __syncthreads();

        #pragma unroll
        for (int ks = 0; ks < BK / 16; ks++) {
            wmma::fragment<wmma::matrix_a, 16, 16, 16, __nv_bfloat16, wmma::row_major> a[4];
            wmma::fragment<wmma::matrix_b, 16, 16, 16, __nv_bfloat16, wmma::col_major> bh[2], bl[2];
            #pragma unroll
            for (int j = 0; j < 2; j++) {
                const __nv_bfloat16* bp0 = Bh_s + (wn * 32 + j * 16) * KPITCH + ks * 16;
                const __nv_bfloat16* bp1 = Bl_s + (wn * 32 + j * 16) * KPITCH + ks * 16;
                wmma::load_matrix_sync(bh[j], bp0, KPITCH);
                wmma::load_matrix_sync(bl[j], bp1, KPITCH);
            }
            #pragma unroll
            for (int i = 0; i < 4; i++)
                wmma::load_matrix_sync(a[i], Ah_s + (wm * 64 + i * 16) * KPITCH + ks * 16, KPITCH);
            // Ah.Bh and Ah.Bl
            #pragma unroll
            for (int i = 0; i < 4; i++)
                #pragma unroll
                for (int j = 0; j < 2; j++) {
                    wmma::mma_sync(acc[i][j], a[i], bh[j], acc[i][j]);
                    wmma::mma_sync(acc[i][j], a[i], bl[j], acc[i][j]);
                }
            // Al.Bh
            #pragma unroll
            for (int i = 0; i < 4; i++)
                wmma::load_matrix_sync(a[i], Al_s + (wm * 64 + i * 16) * KPITCH + ks * 16, KPITCH);
            #pragma unroll
            for (int i = 0; i < 4; i++)
                #pragma unroll
                for (int j = 0; j < 2; j++)
                    wmma::mma_sync(acc[i][j], a[i], bh[j], acc[i][j]);
        }
    }

    // Stage accumulators to smem, then fused epilogue to GMEM.
    __syncthreads();
    #pragma unroll
    for (int i = 0; i < 4; i++)
        #pragma unroll
        for (int j = 0; j < 2; j++) {
            int r0 = wm * 64 + i * 16, c0 = wn * 32 + j * 16;
            wmma::store_matrix_sync(&stg[r0 * SPITCH + c0], acc[i][j], SPITCH, wmma::mem_row_major);
        }
    __syncthreads();

    const int cc = tid & 31;                 // f4 column index (32 per row)
    const int ncol = bx * 128 + cc * 4;
    float4 bb = *(const float4*)&bias[ncol];
    #pragma unroll 4
    for (int rr = 0; rr < 16; rr++) {
        int row = (tid >> 5) * 16 + rr;
        size_t m = arow + row;
        float4 v = *(float4*)&stg[row * SPITCH + cc * 4];
        v.x += bb.x; v.y += bb.y; v.z += bb.z; v.w += bb.w;
        if (GELU_) {
            v.x = gelu_exact(v.x); v.y = gelu_exact(v.y);
            v.z = gelu_exact(v.z); v.w = gelu_exact(v.w);
        }
        if (RES_) {
            float4 rv = *(const float4*)&residual[m * N + ncol];
            v.x += rv.x; v.y += rv.y; v.z += rv.z; v.w += rv.w;
        }
        if (OUTF) *(float4*)&Cf[m * N + ncol] = v;
        if (OUTB) {
            __nv_bfloat16 h[4], l[4];
            split_bf16(v.x, h[0], l[0]); split_bf16(v.y, h[1], l[1]);
            split_bf16(v.z, h[2], l[2]); split_bf16(v.w, h[3], l[3]);
            size_t o = m * N + ncol;
            *(__nv_bfloat162*)&Chi[o]     = __nv_bfloat162(h[0], h[1]);
            *(__nv_bfloat162*)&Chi[o + 2] = __nv_bfloat162(h[2], h[3]);
            *(__nv_bfloat162*)&Clo[o]     = __nv_bfloat162(l[0], l[1]);
            *(__nv_bfloat162*)&Clo[o + 2] = __nv_bfloat162(l[2], l[3]);
        }
    }
}

// ----------------------------------------------------------------------------
// Flash-style causal attention, fp32; emits bf16 hi/lo for Wo GEMM.
// QKV: [B*S, 3072] (Q @ h*64, K @ 1024+h*64, V @ 2048+h*64).
// ----------------------------------------------------------------------------
#define APITCH 68

__global__ void __launch_bounds__(256) attn_kernel(const float* __restrict__ QKV,
                                                   __nv_bfloat16* __restrict__ Ohi,
                                                   __nv_bfloat16* __restrict__ Olo)
{
    extern __shared__ float sm[];
    float* Qs = sm;
    float* Ks = sm + 64 * APITCH;
    float* Vs = sm + 2 * 64 * APITCH;
    float* Ps = sm + 3 * 64 * APITCH;

    int qb = blockIdx.x;
    int bh = blockIdx.y;
    int b = bh >> 4, h = bh & 15;
    int tid = threadIdx.x;
    int r = tid >> 2;
    int q = tid & 3;

    const size_t base = (size_t)b * Sn * 3072 + (size_t)h * 64;

    for (int i = tid; i < 64 * 16; i += 256) {
        int rr = i >> 4, c4 = (i & 15) << 2;
        float4 v = *(const float4*)(QKV + base + (size_t)(qb * 64 + rr) * 3072 + c4);
        float* dst = &Qs[rr * APITCH + c4];
        dst[0] = v.x * 0.125f; dst[1] = v.y * 0.125f;
        dst[2] = v.z * 0.125f; dst[3] = v.w * 0.125f;
    }

    float o[16];
    #pragma unroll
    for (int j = 0; j < 16; j++) o[j] = 0.0f;
    float m_prev = -1e30f, l_prev = 0.0f;
    const int qg = qb * 64 + r;

    for (int kb = 0; kb <= qb; kb++) {
        __syncthreads();
        for (int i = tid; i < 64 * 16; i += 256) {
            int rr = i >> 4, c4 = (i & 15) << 2;
            size_t off = base + (size_t)(kb * 64 + rr) * 3072 + c4;
            *(float4*)&Ks[rr * APITCH + c4] = *(const float4*)(QKV + off + 1024);
            *(float4*)&Vs[rr * APITCH + c4] = *(const float4*)(QKV + off + 2048);
        }
        __syncthreads();

        float s[16];
        #pragma unroll
        for (int j = 0; j < 16; j++) s[j] = 0.0f;
        #pragma unroll 4
        for (int k4 = 0; k4 < 16; k4++) {
            float4 qv = *(const float4*)&Qs[r * APITCH + (k4 << 2)];
            #pragma unroll
            for (int j = 0; j < 16; j++) {
                float4 kv = *(const float4*)&Ks[(q * 16 + j) * APITCH + (k4 << 2)];
                s[j] += qv.x * kv.x + qv.y * kv.y + qv.z * kv.z + qv.w * kv.w;
            }
        }

        float mloc = -1e30f;
        #pragma unroll
        for (int j = 0; j < 16; j++) {
            int tg = kb * 64 + q * 16 + j;
            if (tg > qg) s[j] = -1e30f;
            mloc = fmaxf(mloc, s[j]);
        }
        mloc = fmaxf(mloc, __shfl_xor_sync(0xffffffffu, mloc, 1));
        mloc = fmaxf(mloc, __shfl_xor_sync(0xffffffffu, mloc, 2));

        float m_new = fmaxf(m_prev, mloc);
        float alpha = __expf(m_prev - m_new);

        float lsum = 0.0f;
        #pragma unroll
        for (int j = 0; j < 16; j++) {
            float p = __expf(s[j] - m_new);
            Ps[r * APITCH + q * 16 + j] = p;
            lsum += p;
        }
        lsum += __shfl_xor_sync(0xffffffffu, lsum, 1);
        lsum += __shfl_xor_sync(0xffffffffu, lsum, 2);

        l_prev = l_prev * alpha + lsum;
        m_prev = m_new;
        #pragma unroll
        for (int j = 0; j < 16; j++) o[j] *= alpha;

        __syncwarp();

        #pragma unroll 4
        for (int t = 0; t < 64; t++) {
            float pv = Ps[r * APITCH + t];
            const float* vrow = &Vs[t * APITCH + q * 16];
            float4 v0 = *(const float4*)(vrow + 0);
            float4 v1 = *(const float4*)(vrow + 4);
            float4 v2 = *(const float4*)(vrow + 8);
            float4 v3 = *(const float4*)(vrow + 12);
            o[0]  += pv * v0.x; o[1]  += pv * v0.y; o[2]  += pv * v0.z; o[3]  += pv * v0.w;
            o[4]  += pv * v1.x; o[5]  += pv * v1.y; o[6]  += pv * v1.z; o[7]  += pv * v1.w;
            o[8]  += pv * v2.x; o[9]  += pv * v2.y; o[10] += pv * v2.z; o[11] += pv * v2.w;
            o[12] += pv * v3.x; o[13] += pv * v3.y; o[14] += pv * v3.z; o[15] += pv * v3.w;
        }
    }

    float linv = 1.0f / l_prev;
    size_t ob = (size_t)(b * Sn + qb * 64 + r) * Dn + h * 64 + q * 16;
    #pragma unroll
    for (int j = 0; j < 16; j += 2) {
        float v0 = o[j] * linv, v1 = o[j + 1] * linv;
        __nv_bfloat16 h0, l0, h1, l1;
        split_bf16(v0, h0, l0); split_bf16(v1, h1, l1);
        *(__nv_bfloat162*)&Ohi[ob + j] = __nv_bfloat162(h0, h1);
        *(__nv_bfloat162*)&Olo[ob + j] = __nv_bfloat162(l0, l1);
    }
}

// ----------------------------------------------------------------------------
// Launch
// ----------------------------------------------------------------------------
extern "C" void kernel_launch(void* const* d_in, const int* in_sizes, int n_in,
                              void* d_out, int out_size)
{
    const float* x     = (const float*)d_in[0];
    const float* Wq    = (const float*)d_in[1];
    const float* Wk    = (const float*)d_in[2];
    const float* Wv    = (const float*)d_in[3];
    const float* bq    = (const float*)d_in[4];
    const float* bk    = (const float*)d_in[5];
    const float* bv    = (const float*)d_in[6];
    const float* Wo    = (const float*)d_in[7];
    const float* bo    = (const float*)d_in[8];
    const float* W1    = (const float*)d_in[9];
    const float* b1    = (const float*)d_in[10];
    const float* W2    = (const float*)d_in[11];
    const float* b2    = (const float*)d_in[12];
    const float* gamma = (const float*)d_in[13];
    const float* beta  = (const float*)d_in[14];
    float* out = (float*)d_out;

    float *qkv, *bp;
    __nv_bfloat16 *hAh, *hAl, *ath, *atl, *h1h, *h1l;
    __nv_bfloat16 *wqh, *wql, *woh, *wol, *w1h, *w1l, *w2h, *w2l;
    cudaGetSymbolAddress((void**)&qkv, g_qkv);
    cudaGetSymbolAddress((void**)&bp,  g_bp);
    cudaGetSymbolAddress((void**)&hAh, g_hA_hi); cudaGetSymbolAddress((void**)&hAl, g_hA_lo);
    cudaGetSymbolAddress((void**)&ath, g_at_hi); cudaGetSymbolAddress((void**)&atl, g_at_lo);
    cudaGetSymbolAddress((void**)&h1h, g_h1_hi); cudaGetSymbolAddress((void**)&h1l, g_h1_lo);
    cudaGetSymbolAddress((void**)&wqh, g_wqkvT_hi); cudaGetSymbolAddress((void**)&wql, g_wqkvT_lo);
    cudaGetSymbolAddress((void**)&woh, g_woT_hi);   cudaGetSymbolAddress((void**)&wol, g_woT_lo);
    cudaGetSymbolAddress((void**)&w1h, g_w1T_hi);   cudaGetSymbolAddress((void**)&w1l, g_w1T_lo);
    cudaGetSymbolAddress((void**)&w2h, g_w2T_hi);   cudaGetSymbolAddress((void**)&w2l, g_w2T_lo);

    const int GEMM_SMEM = 4 * TILEB;   // 73728 B (staging 67584 B overlays)
    cudaFuncSetAttribute(mma_gemm_kernel<false, false, true,  false>,
                         cudaFuncAttributeMaxDynamicSharedMemorySize, GEMM_SMEM);
    cudaFuncSetAttribute(mma_gemm_kernel<false, true,  true,  false>,
                         cudaFuncAttributeMaxDynamicSharedMemorySize, GEMM_SMEM);
    cudaFuncSetAttribute(mma_gemm_kernel<true,  false, false, true >,
                         cudaFuncAttributeMaxDynamicSharedMemorySize, GEMM_SMEM);

    // --- weight packing (transpose + bf16 split) ---
    dim3 tb(32, 8);
    transpose_pack_kernel<<<dim3(2, 32, 16), tb>>>(Wq, wqh, wql, Dn, HDn, (long long)Dn * HDn, 0,      Dn);
    transpose_pack_kernel<<<dim3(2, 32, 16), tb>>>(Wk, wqh, wql, Dn, HDn, (long long)Dn * HDn, Dn,     Dn);
    transpose_pack_kernel<<<dim3(2, 32, 16), tb>>>(Wv, wqh, wql, Dn, HDn, (long long)Dn * HDn, 2 * Dn, Dn);
    transpose_pack_kernel<<<dim3(32, 32, 1),  tb>>>(Wo, woh, wol, Dn, Dn, 0, 0, Dn);
    transpose_pack_kernel<<<dim3(128, 32, 1), tb>>>(W1, w1h, w1l, Dn, D4, 0, 0, Dn);
    transpose_pack_kernel<<<dim3(32, 128, 1), tb>>>(W2, w2h, w2l, D4, Dn, 0, 0, D4);
    bias_pack_kernel<<<12, 256>>>(bq, bk, bv, bp);

    // --- LN1 ---
    ln_kernel<<<Mrows, 256>>>(x, gamma, beta, hAh, hAl);

    // --- QKV GEMM: [8192,1024] x [1024,3072] -> fp32 qkv ---
    mma_gemm_kernel<false, false, true, false><<<dim3(3 * Dn / 128, Mrows / 128), 256, GEMM_SMEM>>>(
        hAh, hAl, wqh, wql, bp, nullptr, qkv, nullptr, nullptr, 3 * Dn, Dn);

    // --- attention -> bf16 hi/lo ---
    const int attn_smem = 4 * 64 * APITCH * (int)sizeof(float);
    cudaFuncSetAttribute(attn_kernel, cudaFuncAttributeMaxDynamicSharedMemorySize, attn_smem);
    attn_kernel<<<dim3(Sn / 64, Bn * Hn), 256, attn_smem>>>(qkv, ath, atl);

    // --- Wo GEMM + residual x -> out (fp32) ---
    mma_gemm_kernel<false, true, true, false><<<dim3(Dn / 128, Mrows / 128), 256, GEMM_SMEM>>>(
        ath, atl, woh, wol, bo, x, out, nullptr, nullptr, Dn, Dn);

    // --- LN2 ---
    ln_kernel<<<Mrows, 256>>>(out, gamma, beta, hAh, hAl);

    // --- MLP1 + GELU -> h1 (bf16 hi/lo) ---
    mma_gemm_kernel<true, false, false, true><<<dim3(D4 / 128, Mrows / 128), 256, GEMM_SMEM>>>(
        hAh, hAl, w1h, w1l, b1, nullptr, nullptr, h1h, h1l, D4, Dn);

    // --- MLP2 + residual out -> out (fp32) ---
    mma_gemm_kernel<false, true, true, false><<<dim3(Dn / 128, Mrows / 128), 256, GEMM_SMEM>>>(
        h1h, h1l, w2h, w2l, b2, out, out, nullptr, nullptr, Dn, D4);
}

// round 4
// speedup vs baseline: 1.3287x; 1.0667x over previous
#include <cuda_runtime.h>
#include <cuda_bf16.h>
#include <mma.h>
#include <cstdint>
#include <math.h>

using namespace nvcuda;

// ----------------------------------------------------------------------------
// Problem constants
// ----------------------------------------------------------------------------
#define Bn   4
#define Sn   2048
#define Dn   1024
#define Hn   16
#define HDn  64
#define Mrows (Bn*Sn)          // 8192
#define D4   (4*Dn)            // 4096

// ----------------------------------------------------------------------------
// Scratch (device globals -- no allocations allowed)
// ----------------------------------------------------------------------------
__device__ float         g_qkv  [(size_t)Mrows * 3 * Dn];
__device__ __nv_bfloat16 g_hA_hi[(size_t)Mrows * Dn];
__device__ __nv_bfloat16 g_hA_lo[(size_t)Mrows * Dn];
__device__ __nv_bfloat16 g_at_hi[(size_t)Mrows * Dn];
__device__ __nv_bfloat16 g_at_lo[(size_t)Mrows * Dn];
__device__ __nv_bfloat16 g_h1_hi[(size_t)Mrows * D4];
__device__ __nv_bfloat16 g_h1_lo[(size_t)Mrows * D4];
__device__ __nv_bfloat16 g_wqkvT_hi[(size_t)3 * Dn * Dn];
__device__ __nv_bfloat16 g_wqkvT_lo[(size_t)3 * Dn * Dn];
__device__ __nv_bfloat16 g_woT_hi[(size_t)Dn * Dn];
__device__ __nv_bfloat16 g_woT_lo[(size_t)Dn * Dn];
__device__ __nv_bfloat16 g_w1T_hi[(size_t)D4 * Dn];
__device__ __nv_bfloat16 g_w1T_lo[(size_t)D4 * Dn];
__device__ __nv_bfloat16 g_w2T_hi[(size_t)Dn * D4];
__device__ __nv_bfloat16 g_w2T_lo[(size_t)Dn * D4];
__device__ float         g_bp[3 * Dn];

__device__ __forceinline__ void split_bf16(float v, __nv_bfloat16& h, __nv_bfloat16& l) {
    h = __float2bfloat16(v);
    l = __float2bfloat16(v - __bfloat162float(h));
}

__device__ __forceinline__ uint32_t smem_u32(const void* p) {
    uint32_t a;
    asm("{ .reg .u64 t; cvta.to.shared.u64 t, %1; cvt.u32.u64 %0, t; }" : "=r"(a) : "l"(p));
    return a;
}
__device__ __forceinline__ void cp_async16(void* dst, const void* src) {
    asm volatile("cp.async.cg.shared.global [%0], [%1], 16;"
                 :: "r"(smem_u32(dst)), "l"(src) : "memory");
}
#define CP_COMMIT() asm volatile("cp.async.commit_group;" ::: "memory")
#define CP_WAIT(n)  asm volatile("cp.async.wait_group %0;" :: "n"(n) : "memory")

// ----------------------------------------------------------------------------
// Transpose + bf16 split: src [Ks, Ns] fp32  ->  dst [Ns, Ks] hi/lo bf16 rows.
// ----------------------------------------------------------------------------
__global__ void transpose_pack_kernel(const float* __restrict__ src,
                                      __nv_bfloat16* __restrict__ dhi,
                                      __nv_bfloat16* __restrict__ dlo,
                                      int Ks, int Ns, long long src_zoff,
                                      int out_row_base, int out_stride)
{
    __shared__ float t[32][33];
    int z = blockIdx.z;
    src += (size_t)z * src_zoff;
    int n0 = blockIdx.x * 32, k0 = blockIdx.y * 32;
    int tx = threadIdx.x, ty = threadIdx.y;
    #pragma unroll
    for (int j = 0; j < 4; j++) {
        int k = k0 + ty + j * 8;
        t[ty + j * 8][tx] = src[(size_t)k * Ns + n0 + tx];
    }
    __syncthreads();
    #pragma unroll
    for (int j = 0; j < 4; j++) {
        int n = n0 + ty + j * 8;
        float v = t[tx][ty + j * 8];
        __nv_bfloat16 h, l; split_bf16(v, h, l);
        size_t o = (size_t)(out_row_base + z * Ns + n) * out_stride + k0 + tx;
        dhi[o] = h; dlo[o] = l;
    }
}

__global__ void bias_pack_kernel(const float* __restrict__ bq,
                                 const float* __restrict__ bk,
                                 const float* __restrict__ bv,
                                 float* __restrict__ bp)
{
    int idx = blockIdx.x * 256 + threadIdx.x;
    if (idx < 3 * Dn) {
        int w = idx >> 10, c = idx & 1023;
        bp[idx] = (w == 0 ? bq : w == 1 ? bk : bv)[c];
    }
}

// ----------------------------------------------------------------------------
// LayerNorm -> bf16 hi/lo. One block per row, 256 threads, 4 elems each.
// ----------------------------------------------------------------------------
__global__ void __launch_bounds__(256) ln_kernel(const float* __restrict__ X,
                                                 const float* __restrict__ gamma,
                                                 const float* __restrict__ beta,
                                                 __nv_bfloat16* __restrict__ Yhi,
                                                 __nv_bfloat16* __restrict__ Ylo)
{
    int row = blockIdx.x;
    int tid = threadIdx.x;
    float4 xv = ((const float4*)(X + (size_t)row * Dn))[tid];

    __shared__ float red[8];
    float s = xv.x + xv.y + xv.z + xv.w;
    #pragma unroll
    for (int o = 16; o > 0; o >>= 1) s += __shfl_xor_sync(0xffffffffu, s, o);
    if ((tid & 31) == 0) red[tid >> 5] = s;
    __syncthreads();
    float mu = (red[0]+red[1]+red[2]+red[3]+red[4]+red[5]+red[6]+red[7]) * (1.0f / Dn);
    __syncthreads();

    float dx = xv.x - mu, dy = xv.y - mu, dz = xv.z - mu, dw = xv.w - mu;
    float sq = dx*dx + dy*dy + dz*dz + dw*dw;
    #pragma unroll
    for (int o = 16; o > 0; o >>= 1) sq += __shfl_xor_sync(0xffffffffu, sq, o);
    if ((tid & 31) == 0) red[tid >> 5] = sq;
    __syncthreads();
    float var = (red[0]+red[1]+red[2]+red[3]+red[4]+red[5]+red[6]+red[7]) * (1.0f / Dn);
    float inv = rsqrtf(var + 1e-5f);

    float4 gv = ((const float4*)gamma)[tid];
    float4 bv = ((const float4*)beta)[tid];
    float o0 = dx*inv*gv.x + bv.x, o1 = dy*inv*gv.y + bv.y;
    float o2 = dz*inv*gv.z + bv.z, o3 = dw*inv*gv.w + bv.w;

    __nv_bfloat16 h[4], l[4];
    split_bf16(o0, h[0], l[0]); split_bf16(o1, h[1], l[1]);
    split_bf16(o2, h[2], l[2]); split_bf16(o3, h[3], l[3]);
    size_t off = (size_t)row * Dn + tid * 4;
    *(__nv_bfloat162*)&Yhi[off]     = __nv_bfloat162(h[0], h[1]);
    *(__nv_bfloat162*)&Yhi[off + 2] = __nv_bfloat162(h[2], h[3]);
    *(__nv_bfloat162*)&Ylo[off]     = __nv_bfloat162(l[0], l[1]);
    *(__nv_bfloat162*)&Ylo[off + 2] = __nv_bfloat162(l[2], l[3]);
}

// ----------------------------------------------------------------------------
// WMMA bf16 GEMM with 3-stage cp.async pipeline.
// C[128x128 fp32] = A[128,K] . B^T, hi/lo 3-pass (Ah.Bh + Ah.Bl + Al.Bh).
// Block tile 128x128, BK=64, 8 warps (warp tile 64x32), 256 threads.
// ----------------------------------------------------------------------------
__device__ __forceinline__ float gelu_exact(float v) {
    return 0.5f * v * (1.0f + erff(v * 0.70710678118654752f));
}

#define BK     64
#define KPITCH 72                    // bf16/row (64 + 8 pad)
#define TILEB  (128 * KPITCH * 2)    // 18432 B per matrix tile
#define STAGEB (4 * TILEB)           // 73728 B per stage (Ah, Al, Bh, Bl)
#define NSTAGE 3
#define GEMM_SMEM (NSTAGE * STAGEB)  // 221184 B
#define SPITCH 132                   // fp32 staging pitch

template <bool GELU_, bool RES_, bool OUTF, bool OUTB>
__global__ void __launch_bounds__(256) mma_gemm_kernel(
    const __nv_bfloat16* __restrict__ Ahi, const __nv_bfloat16* __restrict__ Alo,
    const __nv_bfloat16* __restrict__ Bhi, const __nv_bfloat16* __restrict__ Blo,
    const float* __restrict__ bias, const float* __restrict__ residual,
    float* __restrict__ Cf, __nv_bfloat16* __restrict__ Chi, __nv_bfloat16* __restrict__ Clo,
    int N, int K)
{
    extern __shared__ __align__(128) char smem[];
    float* stg = (float*)smem;   // epilogue staging overlays tiles

    const int tid = threadIdx.x;
    const int wid = tid >> 5;
    const int wm = wid >> 2;          // 0..1  (64-row band)
    const int wn = wid & 3;           // 0..3  (32-col band)
    const int bx = blockIdx.x, by = blockIdx.y;

    const size_t arow = (size_t)by * 128;
    const size_t brow = (size_t)bx * 128;

    // per-thread load coords: 512 float4 per matrix per chunk; 2 per thread
    const int l_row0 = tid >> 1;                   // 0..127
    const int l_c0   = (tid & 1) << 3;             // 0 or 8 (f4 slot *? ) -> elems
    // each thread loads rows l_row0 with two 16B segments: cols (tid&1)*32 .. +16
    // simpler mapping: idx = tid + i*256, row = idx>>3, c = idx&7 (8 f4 per row)

    auto load_chunk = [&](int kc, int st) {
        char* base = smem + st * STAGEB;
        __nv_bfloat16* Ah_s = (__nv_bfloat16*)(base + 0 * TILEB);
        __nv_bfloat16* Al_s = (__nv_bfloat16*)(base + 1 * TILEB);
        __nv_bfloat16* Bh_s = (__nv_bfloat16*)(base + 2 * TILEB);
        __nv_bfloat16* Bl_s = (__nv_bfloat16*)(base + 3 * TILEB);
        #pragma unroll
        for (int i = 0; i < 4; i++) {
            int idx = tid + i * 256;
            int row = idx >> 3, c = idx & 7;
            size_t ao = (arow + row) * (size_t)K + kc * BK + c * 8;
            size_t bo = (brow + row) * (size_t)K + kc * BK + c * 8;
            int so = row * KPITCH + c * 8;
            cp_async16(&Ah_s[so], Ahi + ao);
            cp_async16(&Al_s[so], Alo + ao);
            cp_async16(&Bh_s[so], Bhi + bo);
            cp_async16(&Bl_s[so], Blo + bo);
        }
    };

    wmma::fragment<wmma::accumulator, 16, 16, 16, float> acc[4][2];
    #pragma unroll
    for (int i = 0; i < 4; i++)
        #pragma unroll
        for (int j = 0; j < 2; j++) wmma::fill_fragment(acc[i][j], 0.0f);

    const int nk = K / BK;

    // preload stages 0 and 1
    load_chunk(0, 0); CP_COMMIT();
    load_chunk(1, 1); CP_COMMIT();

    for (int kc = 0; kc < nk; kc++) {
        const int st = kc % NSTAGE;
        if (kc + 2 < nk) { load_chunk(kc + 2, (kc + 2) % NSTAGE); CP_COMMIT(); }
        if      (kc + 2 < nk) CP_WAIT(2);
        else if (kc + 1 < nk) CP_WAIT(1);
        else                  CP_WAIT(0);
        __syncthreads();

        char* base = smem + st * STAGEB;
        __nv_bfloat16* Ah_s = (__nv_bfloat16*)(base + 0 * TILEB);
        __nv_bfloat16* Al_s = (__nv_bfloat16*)(base + 1 * TILEB);
        __nv_bfloat16* Bh_s = (__nv_bfloat16*)(base + 2 * TILEB);
        __nv_bfloat16* Bl_s = (__nv_bfloat16*)(base + 3 * TILEB);

        #pragma unroll
        for (int ks = 0; ks < BK / 16; ks++) {
            wmma::fragment<wmma::matrix_a, 16, 16, 16, __nv_bfloat16, wmma::row_major> a[4];
            wmma::fragment<wmma::matrix_b, 16, 16, 16, __nv_bfloat16, wmma::col_major> bh[2], bl[2];
            #pragma unroll
            for (int j = 0; j < 2; j++) {
                wmma::load_matrix_sync(bh[j], Bh_s + (wn * 32 + j * 16) * KPITCH + ks * 16, KPITCH);
                wmma::load_matrix_sync(bl[j], Bl_s + (wn * 32 + j * 16) * KPITCH + ks * 16, KPITCH);
            }
            #pragma unroll
            for (int i = 0; i < 4; i++)
                wmma::load_matrix_sync(a[i], Ah_s + (wm * 64 + i * 16) * KPITCH + ks * 16, KPITCH);
            #pragma unroll
            for (int i = 0; i < 4; i++)
                #pragma unroll
                for (int j = 0; j < 2; j++) {
                    wmma::mma_sync(acc[i][j], a[i], bh[j], acc[i][j]);
                    wmma::mma_sync(acc[i][j], a[i], bl[j], acc[i][j]);
                }
            #pragma unroll
            for (int i = 0; i < 4; i++)
                wmma::load_matrix_sync(a[i], Al_s + (wm * 64 + i * 16) * KPITCH + ks * 16, KPITCH);
            #pragma unroll
            for (int i = 0; i < 4; i++)
                #pragma unroll
                for (int j = 0; j < 2; j++)
                    wmma::mma_sync(acc[i][j], a[i], bh[j], acc[i][j]);
        }
        __syncthreads();
    }

    // Stage accumulators to smem, then fused epilogue to GMEM.
    #pragma unroll
    for (int i = 0; i < 4; i++)
        #pragma unroll
        for (int j = 0; j < 2; j++) {
            int r0 = wm * 64 + i * 16, c0 = wn * 32 + j * 16;
            wmma::store_matrix_sync(&stg[r0 * SPITCH + c0], acc[i][j], SPITCH, wmma::mem_row_major);
        }
    __syncthreads();

    const int cc = tid & 31;
    const int ncol = bx * 128 + cc * 4;
    float4 bb = *(const float4*)&bias[ncol];
    #pragma unroll 4
    for (int rr = 0; rr < 16; rr++) {
        int row = (tid >> 5) * 16 + rr;
        size_t m = arow + row;
        float4 v = *(float4*)&stg[row * SPITCH + cc * 4];
        v.x += bb.x; v.y += bb.y; v.z += bb.z; v.w += bb.w;
        if (GELU_) {
            v.x = gelu_exact(v.x); v.y = gelu_exact(v.y);
            v.z = gelu_exact(v.z); v.w = gelu_exact(v.w);
        }
        if (RES_) {
            float4 rv = *(const float4*)&residual[m * N + ncol];
            v.x += rv.x; v.y += rv.y; v.z += rv.z; v.w += rv.w;
        }
        if (OUTF) *(float4*)&Cf[m * N + ncol] = v;
        if (OUTB) {
            __nv_bfloat16 h[4], l[4];
            split_bf16(v.x, h[0], l[0]); split_bf16(v.y, h[1], l[1]);
            split_bf16(v.z, h[2], l[2]); split_bf16(v.w, h[3], l[3]);
            size_t o = m * N + ncol;
            *(__nv_bfloat162*)&Chi[o]     = __nv_bfloat162(h[0], h[1]);
            *(__nv_bfloat162*)&Chi[o + 2] = __nv_bfloat162(h[2], h[3]);
            *(__nv_bfloat162*)&Clo[o]     = __nv_bfloat162(l[0], l[1]);
            *(__nv_bfloat162*)&Clo[o + 2] = __nv_bfloat162(l[2], l[3]);
        }
    }
}

// ----------------------------------------------------------------------------
// Flash-style causal attention, fp32; emits bf16 hi/lo for Wo GEMM.
// ----------------------------------------------------------------------------
#define APITCH 68

__global__ void __launch_bounds__(256) attn_kernel(const float* __restrict__ QKV,
                                                   __nv_bfloat16* __restrict__ Ohi,
                                                   __nv_bfloat16* __restrict__ Olo)
{
    extern __shared__ float sm[];
    float* Qs = sm;
    float* Ks = sm + 64 * APITCH;
    float* Vs = sm + 2 * 64 * APITCH;
    float* Ps = sm + 3 * 64 * APITCH;

    int qb = blockIdx.x;
    int bh = blockIdx.y;
    int b = bh >> 4, h = bh & 15;
    int tid = threadIdx.x;
    int r = tid >> 2;
    int q = tid & 3;

    const size_t base = (size_t)b * Sn * 3072 + (size_t)h * 64;

    for (int i = tid; i < 64 * 16; i += 256) {
        int rr = i >> 4, c4 = (i & 15) << 2;
        float4 v = *(const float4*)(QKV + base + (size_t)(qb * 64 + rr) * 3072 + c4);
        float* dst = &Qs[rr * APITCH + c4];
        dst[0] = v.x * 0.125f; dst[1] = v.y * 0.125f;
        dst[2] = v.z * 0.125f; dst[3] = v.w * 0.125f;
    }

    float o[16];
    #pragma unroll
    for (int j = 0; j < 16; j++) o[j] = 0.0f;
    float m_prev = -1e30f, l_prev = 0.0f;
    const int qg = qb * 64 + r;

    for (int kb = 0; kb <= qb; kb++) {
        __syncthreads();
        for (int i = tid; i < 64 * 16; i += 256) {
            int rr = i >> 4, c4 = (i & 15) << 2;
            size_t off = base + (size_t)(kb * 64 + rr) * 3072 + c4;
            *(float4*)&Ks[rr * APITCH + c4] = *(const float4*)(QKV + off + 1024);
            *(float4*)&Vs[rr * APITCH + c4] = *(const float4*)(QKV + off + 2048);
        }
        __syncthreads();

        float s[16];
        #pragma unroll
        for (int j = 0; j < 16; j++) s[j] = 0.0f;
        #pragma unroll 4
        for (int k4 = 0; k4 < 16; k4++) {
            float4 qv = *(const float4*)&Qs[r * APITCH + (k4 << 2)];
            #pragma unroll
            for (int j = 0; j < 16; j++) {
                float4 kv = *(const float4*)&Ks[(q * 16 + j) * APITCH + (k4 << 2)];
                s[j] += qv.x * kv.x + qv.y * kv.y + qv.z * kv.z + qv.w * kv.w;
            }
        }

        float mloc = -1e30f;
        #pragma unroll
        for (int j = 0; j < 16; j++) {
            int tg = kb * 64 + q * 16 + j;
            if (tg > qg) s[j] = -1e30f;
            mloc = fmaxf(mloc, s[j]);
        }
        mloc = fmaxf(mloc, __shfl_xor_sync(0xffffffffu, mloc, 1));
        mloc = fmaxf(mloc, __shfl_xor_sync(0xffffffffu, mloc, 2));

        float m_new = fmaxf(m_prev, mloc);
        float alpha = __expf(m_prev - m_new);

        float lsum = 0.0f;
        #pragma unroll
        for (int j = 0; j < 16; j++) {
            float p = __expf(s[j] - m_new);
            Ps[r * APITCH + q * 16 + j] = p;
            lsum += p;
        }
        lsum += __shfl_xor_sync(0xffffffffu, lsum, 1);
        lsum += __shfl_xor_sync(0xffffffffu, lsum, 2);

        l_prev = l_prev * alpha + lsum;
        m_prev = m_new;
        #pragma unroll
        for (int j = 0; j < 16; j++) o[j] *= alpha;

        __syncwarp();

        #pragma unroll 4
        for (int t = 0; t < 64; t++) {
            float pv = Ps[r * APITCH + t];
            const float* vrow = &Vs[t * APITCH + q * 16];
            float4 v0 = *(const float4*)(vrow + 0);
            float4 v1 = *(const float4*)(vrow + 4);
            float4 v2 = *(const float4*)(vrow + 8);
            float4 v3 = *(const float4*)(vrow + 12);
            o[0]  += pv * v0.x; o[1]  += pv * v0.y; o[2]  += pv * v0.z; o[3]  += pv * v0.w;
            o[4]  += pv * v1.x; o[5]  += pv * v1.y; o[6]  += pv * v1.z; o[7]  += pv * v1.w;
            o[8]  += pv * v2.x; o[9]  += pv * v2.y; o[10] += pv * v2.z; o[11] += pv * v2.w;
            o[12] += pv * v3.x; o[13] += pv * v3.y; o[14] += pv * v3.z; o[15] += pv * v3.w;
        }
    }

    float linv = 1.0f / l_prev;
    size_t ob = (size_t)(b * Sn + qb * 64 + r) * Dn + h * 64 + q * 16;
    #pragma unroll
    for (int j = 0; j < 16; j += 2) {
        float v0 = o[j] * linv, v1 = o[j + 1] * linv;
        __nv_bfloat16 h0, l0, h1, l1;
        split_bf16(v0, h0, l0); split_bf16(v1, h1, l1);
        *(__nv_bfloat162*)&Ohi[ob + j] = __nv_bfloat162(h0, h1);
        *(__nv_bfloat162*)&Olo[ob + j] = __nv_bfloat162(l0, l1);
    }
}

// ----------------------------------------------------------------------------
// Launch
// ----------------------------------------------------------------------------
extern "C" void kernel_launch(void* const* d_in, const int* in_sizes, int n_in,
                              void* d_out, int out_size)
{
    const float* x     = (const float*)d_in[0];
    const float* Wq    = (const float*)d_in[1];
    const float* Wk    = (const float*)d_in[2];
    const float* Wv    = (const float*)d_in[3];
    const float* bq    = (const float*)d_in[4];
    const float* bk    = (const float*)d_in[5];
    const float* bv    = (const float*)d_in[6];
    const float* Wo    = (const float*)d_in[7];
    const float* bo    = (const float*)d_in[8];
    const float* W1    = (const float*)d_in[9];
    const float* b1    = (const float*)d_in[10];
    const float* W2    = (const float*)d_in[11];
    const float* b2    = (const float*)d_in[12];
    const float* gamma = (const float*)d_in[13];
    const float* beta  = (const float*)d_in[14];
    float* out = (float*)d_out;

    float *qkv, *bp;
    __nv_bfloat16 *hAh, *hAl, *ath, *atl, *h1h, *h1l;
    __nv_bfloat16 *wqh, *wql, *woh, *wol, *w1h, *w1l, *w2h, *w2l;
    cudaGetSymbolAddress((void**)&qkv, g_qkv);
    cudaGetSymbolAddress((void**)&bp,  g_bp);
    cudaGetSymbolAddress((void**)&hAh, g_hA_hi); cudaGetSymbolAddress((void**)&hAl, g_hA_lo);
    cudaGetSymbolAddress((void**)&ath, g_at_hi); cudaGetSymbolAddress((void**)&atl, g_at_lo);
    cudaGetSymbolAddress((void**)&h1h, g_h1_hi); cudaGetSymbolAddress((void**)&h1l, g_h1_lo);
    cudaGetSymbolAddress((void**)&wqh, g_wqkvT_hi); cudaGetSymbolAddress((void**)&wql, g_wqkvT_lo);
    cudaGetSymbolAddress((void**)&woh, g_woT_hi);   cudaGetSymbolAddress((void**)&wol, g_woT_lo);
    cudaGetSymbolAddress((void**)&w1h, g_w1T_hi);   cudaGetSymbolAddress((void**)&w1l, g_w1T_lo);
    cudaGetSymbolAddress((void**)&w2h, g_w2T_hi);   cudaGetSymbolAddress((void**)&w2l, g_w2T_lo);

    cudaFuncSetAttribute(mma_gemm_kernel<false, false, true,  false>,
                         cudaFuncAttributeMaxDynamicSharedMemorySize, GEMM_SMEM);
    cudaFuncSetAttribute(mma_gemm_kernel<false, true,  true,  false>,
                         cudaFuncAttributeMaxDynamicSharedMemorySize, GEMM_SMEM);
    cudaFuncSetAttribute(mma_gemm_kernel<true,  false, false, true >,
                         cudaFuncAttributeMaxDynamicSharedMemorySize, GEMM_SMEM);

    // --- weight packing (transpose + bf16 split) ---
    dim3 tb(32, 8);
    transpose_pack_kernel<<<dim3(2, 32, 16), tb>>>(Wq, wqh, wql, Dn, HDn, (long long)Dn * HDn, 0,      Dn);
    transpose_pack_kernel<<<dim3(2, 32, 16), tb>>>(Wk, wqh, wql, Dn, HDn, (long long)Dn * HDn, Dn,     Dn);
    transpose_pack_kernel<<<dim3(2, 32, 16), tb>>>(Wv, wqh, wql, Dn, HDn, (long long)Dn * HDn, 2 * Dn, Dn);
    transpose_pack_kernel<<<dim3(32, 32, 1),  tb>>>(Wo, woh, wol, Dn, Dn, 0, 0, Dn);
    transpose_pack_kernel<<<dim3(128, 32, 1), tb>>>(W1, w1h, w1l, Dn, D4, 0, 0, Dn);
    transpose_pack_kernel<<<dim3(32, 128, 1), tb>>>(W2, w2h, w2l, D4, Dn, 0, 0, D4);
    bias_pack_kernel<<<12, 256>>>(bq, bk, bv, bp);

    // --- LN1 ---
    ln_kernel<<<Mrows, 256>>>(x, gamma, beta, hAh, hAl);

    // --- QKV GEMM ---
    mma_gemm_kernel<false, false, true, false><<<dim3(3 * Dn / 128, Mrows / 128), 256, GEMM_SMEM>>>(
        hAh, hAl, wqh, wql, bp, nullptr, qkv, nullptr, nullptr, 3 * Dn, Dn);

    // --- attention ---
    const int attn_smem = 4 * 64 * APITCH * (int)sizeof(float);
    cudaFuncSetAttribute(attn_kernel, cudaFuncAttributeMaxDynamicSharedMemorySize, attn_smem);
    attn_kernel<<<dim3(Sn / 64, Bn * Hn), 256, attn_smem>>>(qkv, ath, atl);

    // --- Wo GEMM + residual ---
    mma_gemm_kernel<false, true, true, false><<<dim3(Dn / 128, Mrows / 128), 256, GEMM_SMEM>>>(
        ath, atl, woh, wol, bo, x, out, nullptr, nullptr, Dn, Dn);

    // --- LN2 ---
    ln_kernel<<<Mrows, 256>>>(out, gamma, beta, hAh, hAl);

    // --- MLP1 + GELU ---
    mma_gemm_kernel<true, false, false, true><<<dim3(D4 / 128, Mrows / 128), 256, GEMM_SMEM>>>(
        hAh, hAl, w1h, w1l, b1, nullptr, nullptr, h1h, h1l, D4, Dn);

    // --- MLP2 + residual ---
    mma_gemm_kernel<false, true, true, false><<<dim3(Dn / 128, Mrows / 128), 256, GEMM_SMEM>>>(
        h1h, h1l, w2h, w2l, b2, out, out, nullptr, nullptr, Dn, D4);
}